// round 2
// baseline (speedup 1.0000x reference)
#include <cuda_runtime.h>

// Problem constants
#define M_   64
#define IN_  64
#define H_   256
#define B_   4096
#define RT   64     // batch rows per CTA tile
#define PAD  68     // padded row length (in floats) for transposed activations
#define NTHR 256

// Dynamic smem layout:
//   actT : [H_][PAD] floats   (transposed activations; rows 0..63 double as xT)
//   wbuf : [32][H_]  floats   (one 32-row weight chunk)
#define SMEM_FLOATS (H_ * PAD + 32 * H_)
#define SMEM_BYTES  (SMEM_FLOATS * 4)

__device__ __forceinline__ void gemm_chunk(const float* __restrict__ actT,
                                           const float* __restrict__ wbuf,
                                           int kbase, int tr, int tc,
                                           float acc[4][16])
{
#pragma unroll 8
    for (int kk = 0; kk < 32; ++kk) {
        float4 a = *(const float4*)&actT[(kbase + kk) * PAD + (tr << 2)];
        const float4* wr = (const float4*)&wbuf[(kk << 8) + (tc << 4)];
        float4 q0 = wr[0], q1 = wr[1], q2 = wr[2], q3 = wr[3];
        float w[16];
        w[0]  = q0.x; w[1]  = q0.y; w[2]  = q0.z; w[3]  = q0.w;
        w[4]  = q1.x; w[5]  = q1.y; w[6]  = q1.z; w[7]  = q1.w;
        w[8]  = q2.x; w[9]  = q2.y; w[10] = q2.z; w[11] = q2.w;
        w[12] = q3.x; w[13] = q3.y; w[14] = q3.z; w[15] = q3.w;
        float av[4] = {a.x, a.y, a.z, a.w};
#pragma unroll
        for (int rr = 0; rr < 4; ++rr)
#pragma unroll
            for (int cc = 0; cc < 16; ++cc)
                acc[rr][cc] = fmaf(av[rr], w[cc], acc[rr][cc]);
    }
}

__global__ __launch_bounds__(NTHR, 1)
void mlp_fused_kernel(const float* __restrict__ xs,
                      const float* __restrict__ W1,
                      const float* __restrict__ b1,
                      const float* __restrict__ W2,
                      const float* __restrict__ b2,
                      const float* __restrict__ W3,
                      const float* __restrict__ b3,
                      float* __restrict__ out)
{
    extern __shared__ float smem[];
    float* actT = smem;                 // [H_][PAD]
    float* wbuf = smem + H_ * PAD;      // [32][H_]

    const int m  = blockIdx.y;
    const int r0 = blockIdx.x * RT;
    const int t  = threadIdx.x;
    const int tc = t & 15;              // column group: cols [tc*16, tc*16+16)
    const int tr = t >> 4;              // row group:    rows [tr*4,  tr*4+4)

    // ---- Stage x tile transposed into actT rows 0..IN_-1 ----
    {
        const float4* xf4 = (const float4*)(xs + ((size_t)m * B_ + r0) * IN_);
        // 64 rows x 16 float4/row = 1024 float4; 4 per thread, coalesced
#pragma unroll
        for (int j = 0; j < 4; ++j) {
            int idx = t + j * NTHR;
            int row = idx >> 4;
            int c4  = idx & 15;
            float4 v = xf4[row * 16 + c4];
            actT[(c4 * 4 + 0) * PAD + row] = v.x;
            actT[(c4 * 4 + 1) * PAD + row] = v.y;
            actT[(c4 * 4 + 2) * PAD + row] = v.z;
            actT[(c4 * 4 + 3) * PAD + row] = v.w;
        }
    }

    float acc[4][16];
#pragma unroll
    for (int rr = 0; rr < 4; ++rr)
#pragma unroll
        for (int cc = 0; cc < 16; ++cc) acc[rr][cc] = 0.f;

    // ---- Layer 1: h1 = relu(x @ W1 + b1), x read from actT rows 0..63 ----
    const float* W1m = W1 + (size_t)m * IN_ * H_;
    for (int kc = 0; kc < IN_ / 32; ++kc) {
        __syncthreads();   // wbuf free to overwrite / actT staging visible
        const float4* src = (const float4*)(W1m + kc * 32 * H_);
        float4* dst = (float4*)wbuf;
#pragma unroll
        for (int j = 0; j < 8; ++j) dst[t + j * NTHR] = src[t + j * NTHR];
        __syncthreads();
        gemm_chunk(actT, wbuf, kc * 32, tr, tc, acc);
    }

    // ---- bias + relu, write h1 transposed into actT rows 0..255 ----
    __syncthreads();   // everyone done reading xT before overwrite
    {
        const float* b1m = b1 + m * H_;
#pragma unroll
        for (int cc = 0; cc < 16; ++cc) {
            int c = tc * 16 + cc;
            float bb = __ldg(&b1m[c]);
            float4 hv;
            hv.x = fmaxf(acc[0][cc] + bb, 0.f);
            hv.y = fmaxf(acc[1][cc] + bb, 0.f);
            hv.z = fmaxf(acc[2][cc] + bb, 0.f);
            hv.w = fmaxf(acc[3][cc] + bb, 0.f);
            *(float4*)&actT[c * PAD + (tr << 2)] = hv;
        }
    }
#pragma unroll
    for (int rr = 0; rr < 4; ++rr)
#pragma unroll
        for (int cc = 0; cc < 16; ++cc) acc[rr][cc] = 0.f;

    // ---- Layer 2: h2 = relu(h1 @ W2 + b2) ----
    const float* W2m = W2 + (size_t)m * H_ * H_;
    for (int kc = 0; kc < H_ / 32; ++kc) {
        __syncthreads();   // also orders the h1 stores above on first iter
        const float4* src = (const float4*)(W2m + kc * 32 * H_);
        float4* dst = (float4*)wbuf;
#pragma unroll
        for (int j = 0; j < 8; ++j) dst[t + j * NTHR] = src[t + j * NTHR];
        __syncthreads();
        gemm_chunk(actT, wbuf, kc * 32, tr, tc, acc);
    }

    // ---- Layer 3 fused epilogue: out = h2 . W3 + b3 (OUT == 1) ----
    {
        const float* b2m = b2 + m * H_;
        const float* W3m = W3 + m * H_;
        float part[4] = {0.f, 0.f, 0.f, 0.f};
#pragma unroll
        for (int cc = 0; cc < 16; ++cc) {
            int c = tc * 16 + cc;
            float bb = __ldg(&b2m[c]);
            float w3 = __ldg(&W3m[c]);
#pragma unroll
            for (int rr = 0; rr < 4; ++rr)
                part[rr] = fmaf(fmaxf(acc[rr][cc] + bb, 0.f), w3, part[rr]);
        }
        // reduce across the 16 column-group lanes (contiguous within a warp)
#pragma unroll
        for (int s = 1; s < 16; s <<= 1)
#pragma unroll
            for (int rr = 0; rr < 4; ++rr)
                part[rr] += __shfl_xor_sync(0xffffffffu, part[rr], s);

        if (tc == 0) {
            float bb3 = __ldg(&b3[m]);
#pragma unroll
            for (int rr = 0; rr < 4; ++rr)
                out[(size_t)m * B_ + r0 + (tr << 2) + rr] = part[rr] + bb3;
        }
    }
}

extern "C" void kernel_launch(void* const* d_in, const int* in_sizes, int n_in,
                              void* d_out, int out_size)
{
    const float* xs = (const float*)d_in[0];
    const float* W1 = (const float*)d_in[1];
    const float* b1 = (const float*)d_in[2];
    const float* W2 = (const float*)d_in[3];
    const float* b2 = (const float*)d_in[4];
    const float* W3 = (const float*)d_in[5];
    const float* b3 = (const float*)d_in[6];
    float* out = (float*)d_out;

    cudaFuncSetAttribute(mlp_fused_kernel,
                         cudaFuncAttributeMaxDynamicSharedMemorySize, SMEM_BYTES);

    dim3 grid(B_ / RT, M_);   // 64 batch tiles x 64 models = 4096 CTAs
    mlp_fused_kernel<<<grid, NTHR, SMEM_BYTES>>>(xs, W1, b1, W2, b2, W3, b3, out);
}

// round 4
// speedup vs baseline: 5.3313x; 5.3313x over previous
#include <cuda_runtime.h>

// ---------------- problem constants ----------------
#define M_   64
#define IN_  64
#define H_   256
#define B_   4096
#define RT   64           // batch rows per CTA
#define NTHR 256

// ---------------- pre-transposed weight scratch (K-major, tf32-rounded) ----
__device__ float g_W1T[M_ * H_ * IN_];   // [m][n=256][k=64]   4 MB
__device__ float g_W2T[M_ * H_ * H_];    // [m][n=256][k=256] 16 MB

// ---------------- smem byte offsets ----------------
// All regions use 128B "k-segment rows": row-major [rows][32 k floats],
// 16B chunks XOR-swizzled by (row & 7).
#define SM_X    0          // X  : 2 ksegs x [64][128B]  = 16384
#define SM_W1   16384      // W1 : 2 ksegs x [256][128B] = 65536
#define SM_H1   81920      // h1 : 8 ksegs x [64][128B]  = 65536
#define SM_W2   147456     // W2 : 2 bufs  x [256][128B] = 65536
#define SM_B1   212992     // b1[256] floats
#define SM_B2   214016
#define SM_W3   215040
#define SM_RED  216064     // red[64][4]
#define SM_TOT  217088

// ---------------- PTX helpers ----------------
__device__ __forceinline__ unsigned smem_u32(const void* p) {
    unsigned a;
    asm("{ .reg .u64 t; cvta.to.shared.u64 t, %1; cvt.u32.u64 %0, t; }" : "=r"(a) : "l"(p));
    return a;
}
__device__ __forceinline__ float to_tf32(float x) {
    unsigned u;
    asm("cvt.rna.tf32.f32 %0, %1;" : "=r"(u) : "f"(x));
    return __uint_as_float(u);
}
__device__ __forceinline__ void cpa16(unsigned dst, const void* src) {
    asm volatile("cp.async.cg.shared.global [%0], [%1], 16;" :: "r"(dst), "l"(src));
}
#define CP_COMMIT()  asm volatile("cp.async.commit_group;" ::: "memory")
#define CP_WAIT(N)   asm volatile("cp.async.wait_group %0;" :: "n"(N) : "memory")

__device__ __forceinline__ void ldsm4(unsigned addr, unsigned r[4]) {
    asm volatile("ldmatrix.sync.aligned.m8n8.x4.shared.b16 {%0,%1,%2,%3}, [%4];"
        : "=r"(r[0]), "=r"(r[1]), "=r"(r[2]), "=r"(r[3]) : "r"(addr));
}
__device__ __forceinline__ void mma8(float c[4], const unsigned a[4],
                                     unsigned b0, unsigned b1) {
    asm volatile("mma.sync.aligned.m16n8k8.row.col.f32.tf32.tf32.f32 "
        "{%0,%1,%2,%3},{%4,%5,%6,%7},{%8,%9},{%0,%1,%2,%3};"
        : "+f"(c[0]), "+f"(c[1]), "+f"(c[2]), "+f"(c[3])
        : "r"(a[0]), "r"(a[1]), "r"(a[2]), "r"(a[3]), "r"(b0), "r"(b1));
}

// one K=8 step: A rows [m0..m0+32), W rows [n0..n0+64), klocal in 0..3
__device__ __forceinline__ void kstep(unsigned Aseg, unsigned Wseg, int kl,
                                      int m0, int n0, int lane,
                                      float acc[2][8][4])
{
    const int rin = lane & 7, sub = lane >> 3;
    unsigned a[2][4], b[4][4];
    {   // A: subtiles {r,c0}{r+8,c0}{r,c1}{r+8,c1}
        int chunk = kl * 2 + (sub >> 1);
        int roff  = rin + (sub & 1) * 8;
#pragma unroll
        for (int mt = 0; mt < 2; ++mt) {
            int row = m0 + mt * 16 + roff;
            ldsm4(Aseg + row * 128 + ((chunk ^ (row & 7)) << 4), a[mt]);
        }
    }
    {   // B: subtiles {n,c0}{n,c1}{n+8,c0}{n+8,c1}  (2 ntiles per x4)
        int chunk = kl * 2 + (sub & 1);
        int roff  = rin + (sub >> 1) * 8;
#pragma unroll
        for (int p = 0; p < 4; ++p) {
            int row = n0 + p * 16 + roff;
            ldsm4(Wseg + row * 128 + ((chunk ^ (row & 7)) << 4), b[p]);
        }
    }
#pragma unroll
    for (int mt = 0; mt < 2; ++mt)
#pragma unroll
        for (int p = 0; p < 4; ++p) {
            mma8(acc[mt][2 * p],     a[mt], b[p][0], b[p][1]);
            mma8(acc[mt][2 * p + 1], a[mt], b[p][2], b[p][3]);
        }
}

// ---------------- transpose + tf32-round kernel ----------------
__global__ void transpose_cvt_kernel(const float* __restrict__ in,
                                     float* __restrict__ out, int K, int N) {
    __shared__ float tile[32][33];
    const int m = blockIdx.z;
    in  += (size_t)m * K * N;
    out += (size_t)m * K * N;
    const int n0 = blockIdx.x * 32, k0 = blockIdx.y * 32;
    const int tx = threadIdx.x, ty = threadIdx.y;
#pragma unroll
    for (int j = ty; j < 32; j += 8)
        tile[j][tx] = in[(size_t)(k0 + j) * N + n0 + tx];
    __syncthreads();
#pragma unroll
    for (int j = ty; j < 32; j += 8)
        out[(size_t)(n0 + j) * K + k0 + tx] = to_tf32(tile[tx][j]);
}

// ---------------- fused MLP kernel ----------------
__global__ __launch_bounds__(NTHR, 1)
void mlp_mma_kernel(const float* __restrict__ xs,
                    const float* __restrict__ b1,
                    const float* __restrict__ b2,
                    const float* __restrict__ w3,
                    const float* __restrict__ b3,
                    float* __restrict__ out)
{
    extern __shared__ char smem[];
    const unsigned sb = smem_u32(smem);
    const int t    = threadIdx.x;
    const int lane = t & 31;
    const int wid  = t >> 5;
    const int m    = blockIdx.y;
    const int r0   = blockIdx.x * RT;
    const int m0   = (wid >> 2) * 32;     // warp row base (0 / 32)
    const int n0   = (wid & 3) * 64;      // warp col base (0/64/128/192)
    const int g    = lane >> 2;
    const int tg   = lane & 3;

    const float* sb1 = (const float*)(smem + SM_B1);
    const float* sb2 = (const float*)(smem + SM_B2);
    const float* sw3 = (const float*)(smem + SM_W3);

    // ---- G0: X + W1 + biases ----
    {   // X tile: 1024 float4
        const float4* src = (const float4*)(xs + ((size_t)m * B_ + r0) * IN_);
#pragma unroll
        for (int i = 0; i < 4; ++i) {
            int idx = t + i * NTHR;
            int row = idx >> 4, c = idx & 15;
            int kseg = c >> 3, cc = c & 7;
            cpa16(sb + SM_X + kseg * 8192 + row * 128 + ((cc ^ (row & 7)) << 4),
                  src + idx);
        }
        // W1: 4096 float4
        const float4* w1s = (const float4*)(g_W1T + (size_t)m * H_ * IN_);
#pragma unroll
        for (int i = 0; i < 16; ++i) {
            int idx = t + i * NTHR;
            int row = idx >> 4, c = idx & 15;
            int kseg = c >> 3, cc = c & 7;
            cpa16(sb + SM_W1 + kseg * 32768 + row * 128 + ((cc ^ (row & 7)) << 4),
                  w1s + idx);
        }
        if (t < 64)  cpa16(sb + SM_B1 + t * 16, (const float4*)(b1 + m * H_) + t);
        else if (t < 128) cpa16(sb + SM_B2 + (t - 64) * 16,
                                (const float4*)(b2 + m * H_) + (t - 64));
        else if (t < 192) cpa16(sb + SM_W3 + (t - 128) * 16,
                                (const float4*)(w3 + m * H_) + (t - 128));
    }
    CP_COMMIT();

    // ---- prefetch W2 chunks 0,1 ----
    const float* w2m = g_W2T + (size_t)m * H_ * H_;
#pragma unroll
    for (int kb = 0; kb < 2; ++kb) {
#pragma unroll
        for (int i = 0; i < 8; ++i) {
            int idx = t + i * NTHR;
            int n = idx >> 3, c = idx & 7;
            cpa16(sb + SM_W2 + kb * 32768 + n * 128 + ((c ^ (n & 7)) << 4),
                  (const float4*)(w2m + n * H_ + kb * 32) + c);
        }
        CP_COMMIT();
    }

    float acc[2][8][4];
#pragma unroll
    for (int mt = 0; mt < 2; ++mt)
#pragma unroll
        for (int nt = 0; nt < 8; ++nt)
#pragma unroll
            for (int j = 0; j < 4; ++j) acc[mt][nt][j] = 0.f;

    // ---- layer 1: K=64, 8 ksteps ----
    CP_WAIT(2);
    __syncthreads();
#pragma unroll
    for (int s = 0; s < 8; ++s)
        kstep(sb + SM_X + (s >> 2) * 8192, sb + SM_W1 + (s >> 2) * 32768,
              s & 3, m0, n0, lane, acc);

    // ---- epilogue 1: h1 = tf32(relu(acc + b1)) -> SM_H1 ----
#pragma unroll
    for (int mt = 0; mt < 2; ++mt)
#pragma unroll
        for (int nt = 0; nt < 8; ++nt) {
            int col = n0 + nt * 8 + 2 * tg;
            float bb0 = sb1[col], bb1 = sb1[col + 1];
            int kseg = col >> 5, colin = col & 31;
            int chunk = colin >> 2, within = colin & 3;
            float* c = acc[mt][nt];
#pragma unroll
            for (int h = 0; h < 2; ++h) {   // h=0: rows g, h=1: rows g+8
                int row = m0 + mt * 16 + g + h * 8;
                float2 v;
                v.x = to_tf32(fmaxf(c[2 * h]     + bb0, 0.f));
                v.y = to_tf32(fmaxf(c[2 * h + 1] + bb1, 0.f));
                *(float2*)(smem + SM_H1 + kseg * 8192 + row * 128 +
                           ((chunk ^ (row & 7)) << 4) + within * 4) = v;
            }
        }
#pragma unroll
    for (int mt = 0; mt < 2; ++mt)
#pragma unroll
        for (int nt = 0; nt < 8; ++nt)
#pragma unroll
            for (int j = 0; j < 4; ++j) acc[mt][nt][j] = 0.f;
    __syncthreads();   // h1 visible

    // ---- layer 2: K=256, 8 chunks x 4 ksteps, double-buffered ----
    for (int kb = 0; kb < 8; ++kb) {
        if (kb == 7) { CP_WAIT(0); } else { CP_WAIT(1); }
        __syncthreads();
        unsigned Aseg = sb + SM_H1 + kb * 8192;
        unsigned Wseg = sb + SM_W2 + (kb & 1) * 32768;
#pragma unroll
        for (int ls = 0; ls < 4; ++ls)
            kstep(Aseg, Wseg, ls, m0, n0, lane, acc);
        if (kb < 6) {
            __syncthreads();   // all warps done with buf (kb&1)
#pragma unroll
            for (int i = 0; i < 8; ++i) {
                int idx = t + i * NTHR;
                int n = idx >> 3, c = idx & 7;
                cpa16(sb + SM_W2 + (kb & 1) * 32768 + n * 128 +
                          ((c ^ (n & 7)) << 4),
                      (const float4*)(w2m + n * H_ + (kb + 2) * 32) + c);
            }
            CP_COMMIT();
        }
    }

    // ---- epilogue 2: out = relu(acc + b2) . w3 + b3 ----
    {
        float part[2][2] = {{0.f, 0.f}, {0.f, 0.f}};
#pragma unroll
        for (int mt = 0; mt < 2; ++mt)
#pragma unroll
            for (int nt = 0; nt < 8; ++nt) {
                int col = n0 + nt * 8 + 2 * tg;
                float bb0 = sb2[col], bb1 = sb2[col + 1];
                float w30 = sw3[col], w31 = sw3[col + 1];
                float* c = acc[mt][nt];
                part[mt][0] = fmaf(fmaxf(c[0] + bb0, 0.f), w30, part[mt][0]);
                part[mt][0] = fmaf(fmaxf(c[1] + bb1, 0.f), w31, part[mt][0]);
                part[mt][1] = fmaf(fmaxf(c[2] + bb0, 0.f), w30, part[mt][1]);
                part[mt][1] = fmaf(fmaxf(c[3] + bb1, 0.f), w31, part[mt][1]);
            }
#pragma unroll
        for (int sfl = 1; sfl < 4; sfl <<= 1)
#pragma unroll
            for (int mt = 0; mt < 2; ++mt) {
                part[mt][0] += __shfl_xor_sync(0xffffffffu, part[mt][0], sfl);
                part[mt][1] += __shfl_xor_sync(0xffffffffu, part[mt][1], sfl);
            }
        float* red = (float*)(smem + SM_RED);
        if (tg == 0) {
#pragma unroll
            for (int mt = 0; mt < 2; ++mt) {
                red[(m0 + mt * 16 + g) * 4     + (wid & 3)] = part[mt][0];
                red[(m0 + mt * 16 + g + 8) * 4 + (wid & 3)] = part[mt][1];
            }
        }
        __syncthreads();
        if (t < RT) {
            float s = red[t * 4] + red[t * 4 + 1] + red[t * 4 + 2] + red[t * 4 + 3];
            out[(size_t)m * B_ + r0 + t] = s + __ldg(b3 + m);
        }
    }
}

// ---------------- launcher ----------------
extern "C" void kernel_launch(void* const* d_in, const int* in_sizes, int n_in,
                              void* d_out, int out_size)
{
    const float* xs = (const float*)d_in[0];
    const float* W1 = (const float*)d_in[1];
    const float* b1 = (const float*)d_in[2];
    const float* W2 = (const float*)d_in[3];
    const float* b2 = (const float*)d_in[4];
    const float* W3 = (const float*)d_in[5];
    const float* b3 = (const float*)d_in[6];
    float* out = (float*)d_out;

    void* p1 = nullptr; void* p2 = nullptr;
    cudaGetSymbolAddress(&p1, g_W1T);
    cudaGetSymbolAddress(&p2, g_W2T);

    dim3 tb(32, 8);
    transpose_cvt_kernel<<<dim3(H_ / 32, IN_ / 32, M_), tb>>>(W1, (float*)p1, IN_, H_);
    transpose_cvt_kernel<<<dim3(H_ / 32, H_ / 32, M_), tb>>>(W2, (float*)p2, H_, H_);

    cudaFuncSetAttribute(mlp_mma_kernel,
                         cudaFuncAttributeMaxDynamicSharedMemorySize, SM_TOT);
    dim3 grid(B_ / RT, M_);   // 64 x 64 = 4096 CTAs
    mlp_mma_kernel<<<grid, NTHR, SM_TOT>>>(xs, b1, b2, W3, b3, out);
}

// round 5
// speedup vs baseline: 6.4621x; 1.2121x over previous
#include <cuda_runtime.h>

// ---------------- problem constants ----------------
#define M_   64
#define IN_  64
#define H_   256
#define B_   4096
#define RT   64           // batch rows per CTA
#define NTHR 256

// ---------------- pre-transposed weight scratch (K-major, tf32-rounded) ----
__device__ float g_W1T[M_ * H_ * IN_];   // [m][n=256][k=64]   4 MB
__device__ float g_W2T[M_ * H_ * H_];    // [m][n=256][k=256] 16 MB

// ---------------- smem byte offsets ----------------
// All regions use 128B "k-segment rows": row-major [rows][32 k floats],
// 16B chunks XOR-swizzled by (row & 7).
// W2 ring: 4 slots x 32 KB. Slots 0,1 live at SM_W2; slots 2,3 overlay SM_W1
// (the W1 region is dead after layer 1).
#define SM_X    0          // X  : 2 ksegs x [64][128B]  = 16384
#define SM_W1   16384      // W1 : 2 ksegs x [256][128B] = 65536   (ring slots 2,3)
#define SM_H1   81920      // h1 : 8 ksegs x [64][128B]  = 65536
#define SM_W2   147456     // ring slots 0,1             = 65536
#define SM_B1   212992     // b1[256] floats
#define SM_B2   214016
#define SM_W3   215040
#define SM_RED  216064     // red[64][4]
#define SM_TOT  217088

#define RING_OFF(s) ((s) < 2 ? (SM_W2 + (s) * 32768) : (SM_W1 + ((s) - 2) * 32768))

// ---------------- PTX helpers ----------------
__device__ __forceinline__ unsigned smem_u32(const void* p) {
    unsigned a;
    asm("{ .reg .u64 t; cvta.to.shared.u64 t, %1; cvt.u32.u64 %0, t; }" : "=r"(a) : "l"(p));
    return a;
}
__device__ __forceinline__ float to_tf32(float x) {
    unsigned u;
    asm("cvt.rna.tf32.f32 %0, %1;" : "=r"(u) : "f"(x));
    return __uint_as_float(u);
}
__device__ __forceinline__ void cpa16(unsigned dst, const void* src) {
    asm volatile("cp.async.cg.shared.global [%0], [%1], 16;" :: "r"(dst), "l"(src));
}
#define CP_COMMIT()  asm volatile("cp.async.commit_group;" ::: "memory")
#define CP_WAIT(N)   asm volatile("cp.async.wait_group %0;" :: "n"(N) : "memory")

__device__ __forceinline__ void ldsm4(unsigned addr, unsigned r[4]) {
    asm volatile("ldmatrix.sync.aligned.m8n8.x4.shared.b16 {%0,%1,%2,%3}, [%4];"
        : "=r"(r[0]), "=r"(r[1]), "=r"(r[2]), "=r"(r[3]) : "r"(addr));
}
__device__ __forceinline__ void mma8(float c[4], const unsigned a[4],
                                     unsigned b0, unsigned b1) {
    asm volatile("mma.sync.aligned.m16n8k8.row.col.f32.tf32.tf32.f32 "
        "{%0,%1,%2,%3},{%4,%5,%6,%7},{%8,%9},{%0,%1,%2,%3};"
        : "+f"(c[0]), "+f"(c[1]), "+f"(c[2]), "+f"(c[3])
        : "r"(a[0]), "r"(a[1]), "r"(a[2]), "r"(a[3]), "r"(b0), "r"(b1));
}

// one K=8 step: A rows [m0..m0+32), W rows [n0..n0+64), klocal in 0..3
__device__ __forceinline__ void kstep(unsigned Aseg, unsigned Wseg, int kl,
                                      int m0, int n0, int lane,
                                      float acc[2][8][4])
{
    const int rin = lane & 7, sub = lane >> 3;
    unsigned a[2][4], b[4][4];
    {   // A: subtiles {r,c0}{r+8,c0}{r,c1}{r+8,c1}
        int chunk = kl * 2 + (sub >> 1);
        int roff  = rin + (sub & 1) * 8;
#pragma unroll
        for (int mt = 0; mt < 2; ++mt) {
            int row = m0 + mt * 16 + roff;
            ldsm4(Aseg + row * 128 + ((chunk ^ (row & 7)) << 4), a[mt]);
        }
    }
    {   // B: subtiles {n,c0}{n,c1}{n+8,c0}{n+8,c1}  (2 ntiles per x4)
        int chunk = kl * 2 + (sub & 1);
        int roff  = rin + (sub >> 1) * 8;
#pragma unroll
        for (int p = 0; p < 4; ++p) {
            int row = n0 + p * 16 + roff;
            ldsm4(Wseg + row * 128 + ((chunk ^ (row & 7)) << 4), b[p]);
        }
    }
#pragma unroll
    for (int mt = 0; mt < 2; ++mt)
#pragma unroll
        for (int p = 0; p < 4; ++p) {
            mma8(acc[mt][2 * p],     a[mt], b[p][0], b[p][1]);
            mma8(acc[mt][2 * p + 1], a[mt], b[p][2], b[p][3]);
        }
}

// ---------------- merged transpose + tf32-round kernel ----------------
// y-tile 0..1  -> W1 (K=64),  y-tile 2..9 -> W2 (K=256)
__global__ void transpose_cvt_all(const float* __restrict__ W1,
                                  const float* __restrict__ W2,
                                  float* __restrict__ W1T,
                                  float* __restrict__ W2T)
{
    __shared__ float tile[32][33];
    const int m = blockIdx.z;
    const float* in;
    float* out;
    int K, kt;
    if (blockIdx.y < 2) { in = W1; out = W1T; K = IN_; kt = blockIdx.y; }
    else                { in = W2; out = W2T; K = H_;  kt = blockIdx.y - 2; }
    in  += (size_t)m * K * H_;
    out += (size_t)m * K * H_;
    const int n0 = blockIdx.x * 32, k0 = kt * 32;
    const int tx = threadIdx.x, ty = threadIdx.y;
#pragma unroll
    for (int j = ty; j < 32; j += 8)
        tile[j][tx] = in[(size_t)(k0 + j) * H_ + n0 + tx];
    __syncthreads();
#pragma unroll
    for (int j = ty; j < 32; j += 8)
        out[(size_t)(n0 + j) * K + k0 + tx] = to_tf32(tile[tx][j]);
}

// ---------------- fused MLP kernel ----------------
__global__ __launch_bounds__(NTHR, 1)
void mlp_mma_kernel(const float* __restrict__ xs,
                    const float* __restrict__ b1,
                    const float* __restrict__ b2,
                    const float* __restrict__ w3,
                    const float* __restrict__ b3,
                    float* __restrict__ out)
{
    extern __shared__ char smem[];
    const unsigned sb = smem_u32(smem);
    const int t    = threadIdx.x;
    const int lane = t & 31;
    const int wid  = t >> 5;
    const int m    = blockIdx.y;
    const int r0   = blockIdx.x * RT;
    const int m0   = (wid >> 2) * 32;     // warp row base (0 / 32)
    const int n0   = (wid & 3) * 64;      // warp col base (0/64/128/192)
    const int g    = lane >> 2;
    const int tg   = lane & 3;

    const float* sb1 = (const float*)(smem + SM_B1);
    const float* sb2 = (const float*)(smem + SM_B2);
    const float* sw3 = (const float*)(smem + SM_W3);
    const float* w2m = g_W2T + (size_t)m * H_ * H_;

    // ---- G0: X + W1 + biases ----
    {   // X tile: 1024 float4
        const float4* src = (const float4*)(xs + ((size_t)m * B_ + r0) * IN_);
#pragma unroll
        for (int i = 0; i < 4; ++i) {
            int idx = t + i * NTHR;
            int row = idx >> 4, c = idx & 15;
            int kseg = c >> 3, cc = c & 7;
            cpa16(sb + SM_X + kseg * 8192 + row * 128 + ((cc ^ (row & 7)) << 4),
                  src + idx);
        }
        // W1: 4096 float4
        const float4* w1s = (const float4*)(g_W1T + (size_t)m * H_ * IN_);
#pragma unroll
        for (int i = 0; i < 16; ++i) {
            int idx = t + i * NTHR;
            int row = idx >> 4, c = idx & 15;
            int kseg = c >> 3, cc = c & 7;
            cpa16(sb + SM_W1 + kseg * 32768 + row * 128 + ((cc ^ (row & 7)) << 4),
                  w1s + idx);
        }
        if (t < 64)  cpa16(sb + SM_B1 + t * 16, (const float4*)(b1 + m * H_) + t);
        else if (t < 128) cpa16(sb + SM_B2 + (t - 64) * 16,
                                (const float4*)(b2 + m * H_) + (t - 64));
        else if (t < 192) cpa16(sb + SM_W3 + (t - 128) * 16,
                                (const float4*)(w3 + m * H_) + (t - 128));
    }
    CP_COMMIT();

    // ---- G1,G2: prefetch W2 chunks 0,1 into ring slots 0,1 ----
#pragma unroll
    for (int kb = 0; kb < 2; ++kb) {
#pragma unroll
        for (int i = 0; i < 8; ++i) {
            int idx = t + i * NTHR;
            int n = idx >> 3, c = idx & 7;
            cpa16(sb + RING_OFF(kb) + n * 128 + ((c ^ (n & 7)) << 4),
                  (const float4*)(w2m + n * H_ + kb * 32) + c);
        }
        CP_COMMIT();
    }

    float acc[2][8][4];
#pragma unroll
    for (int mt = 0; mt < 2; ++mt)
#pragma unroll
        for (int nt = 0; nt < 8; ++nt)
#pragma unroll
            for (int j = 0; j < 4; ++j) acc[mt][nt][j] = 0.f;

    // ---- layer 1: K=64, 8 ksteps ----
    CP_WAIT(2);            // G0 done; G1,G2 may still be pending
    __syncthreads();
#pragma unroll
    for (int s = 0; s < 8; ++s)
        kstep(sb + SM_X + (s >> 2) * 8192, sb + SM_W1 + (s >> 2) * 32768,
              s & 3, m0, n0, lane, acc);

    // ---- epilogue 1: h1 = tf32(relu(acc + b1)) -> SM_H1 ----
#pragma unroll
    for (int mt = 0; mt < 2; ++mt)
#pragma unroll
        for (int nt = 0; nt < 8; ++nt) {
            int col = n0 + nt * 8 + 2 * tg;
            float bb0 = sb1[col], bb1 = sb1[col + 1];
            int kseg = col >> 5, colin = col & 31;
            int chunk = colin >> 2, within = colin & 3;
            float* c = acc[mt][nt];
#pragma unroll
            for (int h = 0; h < 2; ++h) {   // h=0: rows g, h=1: rows g+8
                int row = m0 + mt * 16 + g + h * 8;
                float2 v;
                v.x = to_tf32(fmaxf(c[2 * h]     + bb0, 0.f));
                v.y = to_tf32(fmaxf(c[2 * h + 1] + bb1, 0.f));
                *(float2*)(smem + SM_H1 + kseg * 8192 + row * 128 +
                           ((chunk ^ (row & 7)) << 4) + within * 4) = v;
            }
        }
#pragma unroll
    for (int mt = 0; mt < 2; ++mt)
#pragma unroll
        for (int nt = 0; nt < 8; ++nt)
#pragma unroll
            for (int j = 0; j < 4; ++j) acc[mt][nt][j] = 0.f;
    __syncthreads();   // h1 visible; all warps past layer-1 (W1 region now dead)

    // ---- G3: chunk 2 into ring slot 2 (overlays W1) ----
    {
#pragma unroll
        for (int i = 0; i < 8; ++i) {
            int idx = t + i * NTHR;
            int n = idx >> 3, c = idx & 7;
            cpa16(sb + RING_OFF(2) + n * 128 + ((c ^ (n & 7)) << 4),
                  (const float4*)(w2m + n * H_ + 2 * 32) + c);
        }
        CP_COMMIT();
    }

    // ---- layer 2: K=256, 8 chunks, 4-slot ring, distance-3 prefetch ----
#pragma unroll
    for (int kb = 0; kb < 8; ++kb) {
        // wait for chunk kb; allowed pending = min(2, 7-kb)
        if (kb <= 5)      { CP_WAIT(2); }
        else if (kb == 6) { CP_WAIT(1); }
        else              { CP_WAIT(0); }
        __syncthreads();   // chunk kb visible; all warps done with chunk kb-1
        if (kb + 3 <= 7) { // prefetch chunk kb+3 into slot (kb+3)&3 (= slot of kb-1)
            const int pc = kb + 3;
#pragma unroll
            for (int i = 0; i < 8; ++i) {
                int idx = t + i * NTHR;
                int n = idx >> 3, c = idx & 7;
                cpa16(sb + RING_OFF(pc & 3) + n * 128 + ((c ^ (n & 7)) << 4),
                      (const float4*)(w2m + n * H_ + pc * 32) + c);
            }
            CP_COMMIT();
        }
        unsigned Aseg = sb + SM_H1 + kb * 8192;
        unsigned Wseg = sb + RING_OFF(kb & 3);
#pragma unroll
        for (int ls = 0; ls < 4; ++ls)
            kstep(Aseg, Wseg, ls, m0, n0, lane, acc);
    }

    // ---- epilogue 2: out = relu(acc + b2) . w3 + b3 ----
    {
        float part[2][2] = {{0.f, 0.f}, {0.f, 0.f}};
#pragma unroll
        for (int mt = 0; mt < 2; ++mt)
#pragma unroll
            for (int nt = 0; nt < 8; ++nt) {
                int col = n0 + nt * 8 + 2 * tg;
                float bb0 = sb2[col], bb1 = sb2[col + 1];
                float w30 = sw3[col], w31 = sw3[col + 1];
                float* c = acc[mt][nt];
                part[mt][0] = fmaf(fmaxf(c[0] + bb0, 0.f), w30, part[mt][0]);
                part[mt][0] = fmaf(fmaxf(c[1] + bb1, 0.f), w31, part[mt][0]);
                part[mt][1] = fmaf(fmaxf(c[2] + bb0, 0.f), w30, part[mt][1]);
                part[mt][1] = fmaf(fmaxf(c[3] + bb1, 0.f), w31, part[mt][1]);
            }
#pragma unroll
        for (int sfl = 1; sfl < 4; sfl <<= 1)
#pragma unroll
            for (int mt = 0; mt < 2; ++mt) {
                part[mt][0] += __shfl_xor_sync(0xffffffffu, part[mt][0], sfl);
                part[mt][1] += __shfl_xor_sync(0xffffffffu, part[mt][1], sfl);
            }
        float* red = (float*)(smem + SM_RED);
        if (tg == 0) {
#pragma unroll
            for (int mt = 0; mt < 2; ++mt) {
                red[(m0 + mt * 16 + g) * 4     + (wid & 3)] = part[mt][0];
                red[(m0 + mt * 16 + g + 8) * 4 + (wid & 3)] = part[mt][1];
            }
        }
        __syncthreads();
        if (t < RT) {
            float s = red[t * 4] + red[t * 4 + 1] + red[t * 4 + 2] + red[t * 4 + 3];
            out[(size_t)m * B_ + r0 + t] = s + __ldg(b3 + m);
        }
    }
}

// ---------------- launcher ----------------
extern "C" void kernel_launch(void* const* d_in, const int* in_sizes, int n_in,
                              void* d_out, int out_size)
{
    const float* xs = (const float*)d_in[0];
    const float* W1 = (const float*)d_in[1];
    const float* b1 = (const float*)d_in[2];
    const float* W2 = (const float*)d_in[3];
    const float* b2 = (const float*)d_in[4];
    const float* W3 = (const float*)d_in[5];
    const float* b3 = (const float*)d_in[6];
    float* out = (float*)d_out;

    void* p1 = nullptr; void* p2 = nullptr;
    cudaGetSymbolAddress(&p1, g_W1T);
    cudaGetSymbolAddress(&p2, g_W2T);

    dim3 tb(32, 8);
    transpose_cvt_all<<<dim3(H_ / 32, 10, M_), tb>>>(W1, W2, (float*)p1, (float*)p2);

    cudaFuncSetAttribute(mlp_mma_kernel,
                         cudaFuncAttributeMaxDynamicSharedMemorySize, SM_TOT);
    dim3 grid(B_ / RT, M_);   // 64 x 64 = 4096 CTAs
    mlp_mma_kernel<<<grid, NTHR, SM_TOT>>>(xs, b1, b2, W3, b3, out);
}

// round 6
// speedup vs baseline: 9.0609x; 1.4021x over previous
#include <cuda_runtime.h>

// ---------------- problem constants ----------------
#define M_   64
#define IN_  64
#define H_   256
#define B_   4096
#define RT   64           // batch rows per CTA
#define NTHR 512          // 16 warps, warp tile 32x32

// ---------------- pre-transposed weight scratch (K-major, tf32-rounded) ----
__device__ float g_W1T[M_ * H_ * IN_];   // [m][n=256][k=64]   4 MB
__device__ float g_W2T[M_ * H_ * H_];    // [m][n=256][k=256] 16 MB

// ---------------- smem byte offsets ----------------
// 128B "k-segment rows": row-major [rows][32 k floats], 16B chunks XOR-swizzled
// by (row & 7). W2 ring: 4 slots x 32 KB (slots 2,3 overlay dead W1 region).
#define SM_X    0          // X  : 2 ksegs x [64][128B]  = 16384
#define SM_W1   16384      // W1 : 2 ksegs x [256][128B] = 65536   (ring slots 2,3)
#define SM_H1   81920      // h1 : 8 ksegs x [64][128B]  = 65536
#define SM_W2   147456     // ring slots 0,1             = 65536
#define SM_B1   212992     // b1[256] floats
#define SM_B2   214016
#define SM_W3   215040
#define SM_RED  216064     // red[64][8]
#define SM_TOT  218112

#define RING_OFF(s) ((s) < 2 ? (SM_W2 + (s) * 32768) : (SM_W1 + ((s) - 2) * 32768))

// ---------------- PTX helpers ----------------
__device__ __forceinline__ unsigned smem_u32(const void* p) {
    unsigned a;
    asm("{ .reg .u64 t; cvta.to.shared.u64 t, %1; cvt.u32.u64 %0, t; }" : "=r"(a) : "l"(p));
    return a;
}
__device__ __forceinline__ float to_tf32(float x) {
    unsigned u;
    asm("cvt.rna.tf32.f32 %0, %1;" : "=r"(u) : "f"(x));
    return __uint_as_float(u);
}
__device__ __forceinline__ void cpa16(unsigned dst, const void* src) {
    asm volatile("cp.async.cg.shared.global [%0], [%1], 16;" :: "r"(dst), "l"(src));
}
#define CP_COMMIT()  asm volatile("cp.async.commit_group;" ::: "memory")
#define CP_WAIT(N)   asm volatile("cp.async.wait_group %0;" :: "n"(N) : "memory")

__device__ __forceinline__ void ldsm4(unsigned addr, unsigned r[4]) {
    asm volatile("ldmatrix.sync.aligned.m8n8.x4.shared.b16 {%0,%1,%2,%3}, [%4];"
        : "=r"(r[0]), "=r"(r[1]), "=r"(r[2]), "=r"(r[3]) : "r"(addr));
}
__device__ __forceinline__ void mma8(float c[4], const unsigned a[4],
                                     unsigned b0, unsigned b1) {
    asm volatile("mma.sync.aligned.m16n8k8.row.col.f32.tf32.tf32.f32 "
        "{%0,%1,%2,%3},{%4,%5,%6,%7},{%8,%9},{%0,%1,%2,%3};"
        : "+f"(c[0]), "+f"(c[1]), "+f"(c[2]), "+f"(c[3])
        : "r"(a[0]), "r"(a[1]), "r"(a[2]), "r"(a[3]), "r"(b0), "r"(b1));
}

// one K=8 step, warp tile 32x32: A rows [m0..m0+32), W rows [n0..n0+32)
__device__ __forceinline__ void kstep(unsigned Aseg, unsigned Wseg, int kl,
                                      int m0, int n0, int lane,
                                      float acc[2][4][4])
{
    const int rin = lane & 7, sub = lane >> 3;
    unsigned a[2][4], b[2][4];
    {   // A: subtiles {r,c0}{r+8,c0}{r,c1}{r+8,c1}
        int chunk = kl * 2 + (sub >> 1);
        int roff  = rin + (sub & 1) * 8;
#pragma unroll
        for (int mt = 0; mt < 2; ++mt) {
            int row = m0 + mt * 16 + roff;
            ldsm4(Aseg + row * 128 + ((chunk ^ (row & 7)) << 4), a[mt]);
        }
    }
    {   // B: subtiles {n,c0}{n,c1}{n+8,c0}{n+8,c1}  (2 ntiles per x4)
        int chunk = kl * 2 + (sub & 1);
        int roff  = rin + (sub >> 1) * 8;
#pragma unroll
        for (int p = 0; p < 2; ++p) {
            int row = n0 + p * 16 + roff;
            ldsm4(Wseg + row * 128 + ((chunk ^ (row & 7)) << 4), b[p]);
        }
    }
#pragma unroll
    for (int mt = 0; mt < 2; ++mt)
#pragma unroll
        for (int p = 0; p < 2; ++p) {
            mma8(acc[mt][2 * p],     a[mt], b[p][0], b[p][1]);
            mma8(acc[mt][2 * p + 1], a[mt], b[p][2], b[p][3]);
        }
}

// ---------------- merged transpose + tf32-round kernel ----------------
__global__ void transpose_cvt_all(const float* __restrict__ W1,
                                  const float* __restrict__ W2,
                                  float* __restrict__ W1T,
                                  float* __restrict__ W2T)
{
    __shared__ float tile[32][33];
    const int m = blockIdx.z;
    const float* in;
    float* out;
    int K, kt;
    if (blockIdx.y < 2) { in = W1; out = W1T; K = IN_; kt = blockIdx.y; }
    else                { in = W2; out = W2T; K = H_;  kt = blockIdx.y - 2; }
    in  += (size_t)m * K * H_;
    out += (size_t)m * K * H_;
    const int n0 = blockIdx.x * 32, k0 = kt * 32;
    const int tx = threadIdx.x, ty = threadIdx.y;
#pragma unroll
    for (int j = ty; j < 32; j += 8)
        tile[j][tx] = in[(size_t)(k0 + j) * H_ + n0 + tx];
    __syncthreads();
#pragma unroll
    for (int j = ty; j < 32; j += 8)
        out[(size_t)(n0 + j) * K + k0 + tx] = to_tf32(tile[tx][j]);
}

// ---------------- fused MLP kernel ----------------
__global__ __launch_bounds__(NTHR, 1)
void mlp_mma_kernel(const float* __restrict__ xs,
                    const float* __restrict__ b1,
                    const float* __restrict__ b2,
                    const float* __restrict__ w3,
                    const float* __restrict__ b3,
                    float* __restrict__ out)
{
    extern __shared__ char smem[];
    const unsigned sb = smem_u32(smem);
    const int t    = threadIdx.x;
    const int lane = t & 31;
    const int wid  = t >> 5;
    const int m    = blockIdx.y;
    const int r0   = blockIdx.x * RT;
    const int m0   = (wid >> 3) * 32;     // warp row base (0 / 32)
    const int n0   = (wid & 7) * 32;      // warp col base (0..224)
    const int g    = lane >> 2;
    const int tg   = lane & 3;

    const float* sb1 = (const float*)(smem + SM_B1);
    const float* sb2 = (const float*)(smem + SM_B2);
    const float* sw3 = (const float*)(smem + SM_W3);
    const float* w2m = g_W2T + (size_t)m * H_ * H_;

    // ---- G0: X + W1 + biases ----
    {   // X tile: 1024 float4
        const float4* src = (const float4*)(xs + ((size_t)m * B_ + r0) * IN_);
#pragma unroll
        for (int i = 0; i < 2; ++i) {
            int idx = t + i * NTHR;
            int row = idx >> 4, c = idx & 15;
            int kseg = c >> 3, cc = c & 7;
            cpa16(sb + SM_X + kseg * 8192 + row * 128 + ((cc ^ (row & 7)) << 4),
                  src + idx);
        }
        // W1: 4096 float4
        const float4* w1s = (const float4*)(g_W1T + (size_t)m * H_ * IN_);
#pragma unroll
        for (int i = 0; i < 8; ++i) {
            int idx = t + i * NTHR;
            int row = idx >> 4, c = idx & 15;
            int kseg = c >> 3, cc = c & 7;
            cpa16(sb + SM_W1 + kseg * 32768 + row * 128 + ((cc ^ (row & 7)) << 4),
                  w1s + idx);
        }
        if (t < 64)  cpa16(sb + SM_B1 + t * 16, (const float4*)(b1 + m * H_) + t);
        else if (t < 128) cpa16(sb + SM_B2 + (t - 64) * 16,
                                (const float4*)(b2 + m * H_) + (t - 64));
        else if (t < 192) cpa16(sb + SM_W3 + (t - 128) * 16,
                                (const float4*)(w3 + m * H_) + (t - 128));
    }
    CP_COMMIT();

    // ---- G1,G2: prefetch W2 chunks 0,1 into ring slots 0,1 ----
#pragma unroll
    for (int kb = 0; kb < 2; ++kb) {
#pragma unroll
        for (int i = 0; i < 4; ++i) {
            int idx = t + i * NTHR;
            int n = idx >> 3, c = idx & 7;
            cpa16(sb + RING_OFF(kb) + n * 128 + ((c ^ (n & 7)) << 4),
                  (const float4*)(w2m + n * H_ + kb * 32) + c);
        }
        CP_COMMIT();
    }

    float acc[2][4][4];
#pragma unroll
    for (int mt = 0; mt < 2; ++mt)
#pragma unroll
        for (int nt = 0; nt < 4; ++nt)
#pragma unroll
            for (int j = 0; j < 4; ++j) acc[mt][nt][j] = 0.f;

    // ---- layer 1: K=64, 8 ksteps ----
    CP_WAIT(2);            // G0 done; G1,G2 may still be pending
    __syncthreads();
#pragma unroll
    for (int s = 0; s < 8; ++s)
        kstep(sb + SM_X + (s >> 2) * 8192, sb + SM_W1 + (s >> 2) * 32768,
              s & 3, m0, n0, lane, acc);

    // ---- epilogue 1: h1 = tf32(relu(acc + b1)) -> SM_H1 ----
#pragma unroll
    for (int mt = 0; mt < 2; ++mt)
#pragma unroll
        for (int nt = 0; nt < 4; ++nt) {
            int col = n0 + nt * 8 + 2 * tg;
            float bb0 = sb1[col], bb1 = sb1[col + 1];
            int kseg = col >> 5, colin = col & 31;
            int chunk = colin >> 2, within = colin & 3;
            float* c = acc[mt][nt];
#pragma unroll
            for (int h = 0; h < 2; ++h) {   // h=0: rows g, h=1: rows g+8
                int row = m0 + mt * 16 + g + h * 8;
                float2 v;
                v.x = to_tf32(fmaxf(c[2 * h]     + bb0, 0.f));
                v.y = to_tf32(fmaxf(c[2 * h + 1] + bb1, 0.f));
                *(float2*)(smem + SM_H1 + kseg * 8192 + row * 128 +
                           ((chunk ^ (row & 7)) << 4) + within * 4) = v;
            }
        }
#pragma unroll
    for (int mt = 0; mt < 2; ++mt)
#pragma unroll
        for (int nt = 0; nt < 4; ++nt)
#pragma unroll
            for (int j = 0; j < 4; ++j) acc[mt][nt][j] = 0.f;
    __syncthreads();   // h1 visible; all warps past layer-1 (W1 region now dead)

    // ---- G3: chunk 2 into ring slot 2 (overlays W1) ----
    {
#pragma unroll
        for (int i = 0; i < 4; ++i) {
            int idx = t + i * NTHR;
            int n = idx >> 3, c = idx & 7;
            cpa16(sb + RING_OFF(2) + n * 128 + ((c ^ (n & 7)) << 4),
                  (const float4*)(w2m + n * H_ + 2 * 32) + c);
        }
        CP_COMMIT();
    }

    // ---- layer 2: K=256, 8 chunks, 4-slot ring, distance-3 prefetch ----
#pragma unroll
    for (int kb = 0; kb < 8; ++kb) {
        if (kb <= 5)      { CP_WAIT(2); }
        else if (kb == 6) { CP_WAIT(1); }
        else              { CP_WAIT(0); }
        __syncthreads();   // chunk kb visible; all warps done with chunk kb-1
        if (kb + 3 <= 7) {
            const int pc = kb + 3;
#pragma unroll
            for (int i = 0; i < 4; ++i) {
                int idx = t + i * NTHR;
                int n = idx >> 3, c = idx & 7;
                cpa16(sb + RING_OFF(pc & 3) + n * 128 + ((c ^ (n & 7)) << 4),
                      (const float4*)(w2m + n * H_ + pc * 32) + c);
            }
            CP_COMMIT();
        }
        unsigned Aseg = sb + SM_H1 + kb * 8192;
        unsigned Wseg = sb + RING_OFF(kb & 3);
#pragma unroll
        for (int ls = 0; ls < 4; ++ls)
            kstep(Aseg, Wseg, ls, m0, n0, lane, acc);
    }

    // ---- epilogue 2: out = relu(acc + b2) . w3 + b3 ----
    {
        float part[2][2] = {{0.f, 0.f}, {0.f, 0.f}};
#pragma unroll
        for (int mt = 0; mt < 2; ++mt)
#pragma unroll
            for (int nt = 0; nt < 4; ++nt) {
                int col = n0 + nt * 8 + 2 * tg;
                float bb0 = sb2[col], bb1 = sb2[col + 1];
                float w30 = sw3[col], w31 = sw3[col + 1];
                float* c = acc[mt][nt];
                part[mt][0] = fmaf(fmaxf(c[0] + bb0, 0.f), w30, part[mt][0]);
                part[mt][0] = fmaf(fmaxf(c[1] + bb1, 0.f), w31, part[mt][0]);
                part[mt][1] = fmaf(fmaxf(c[2] + bb0, 0.f), w30, part[mt][1]);
                part[mt][1] = fmaf(fmaxf(c[3] + bb1, 0.f), w31, part[mt][1]);
            }
#pragma unroll
        for (int sfl = 1; sfl < 4; sfl <<= 1)
#pragma unroll
            for (int mt = 0; mt < 2; ++mt) {
                part[mt][0] += __shfl_xor_sync(0xffffffffu, part[mt][0], sfl);
                part[mt][1] += __shfl_xor_sync(0xffffffffu, part[mt][1], sfl);
            }
        float* red = (float*)(smem + SM_RED);
        if (tg == 0) {
#pragma unroll
            for (int mt = 0; mt < 2; ++mt) {
                red[(m0 + mt * 16 + g) * 8     + (wid & 7)] = part[mt][0];
                red[(m0 + mt * 16 + g + 8) * 8 + (wid & 7)] = part[mt][1];
            }
        }
        __syncthreads();
        if (t < RT) {
            const float* r = red + t * 8;
            float s = ((r[0] + r[1]) + (r[2] + r[3])) +
                      ((r[4] + r[5]) + (r[6] + r[7]));
            out[(size_t)m * B_ + r0 + t] = s + __ldg(b3 + m);
        }
    }
}

// ---------------- launcher ----------------
extern "C" void kernel_launch(void* const* d_in, const int* in_sizes, int n_in,
                              void* d_out, int out_size)
{
    const float* xs = (const float*)d_in[0];
    const float* W1 = (const float*)d_in[1];
    const float* b1 = (const float*)d_in[2];
    const float* W2 = (const float*)d_in[3];
    const float* b2 = (const float*)d_in[4];
    const float* W3 = (const float*)d_in[5];
    const float* b3 = (const float*)d_in[6];
    float* out = (float*)d_out;

    void* p1 = nullptr; void* p2 = nullptr;
    cudaGetSymbolAddress(&p1, g_W1T);
    cudaGetSymbolAddress(&p2, g_W2T);

    dim3 tb(32, 8);
    transpose_cvt_all<<<dim3(H_ / 32, 10, M_), tb>>>(W1, W2, (float*)p1, (float*)p2);

    cudaFuncSetAttribute(mlp_mma_kernel,
                         cudaFuncAttributeMaxDynamicSharedMemorySize, SM_TOT);
    dim3 grid(B_ / RT, M_);   // 64 x 64 = 4096 CTAs
    mlp_mma_kernel<<<grid, NTHR, SM_TOT>>>(xs, b1, b2, W3, b3, out);
}